// round 16
// baseline (speedup 1.0000x reference)
#include <cuda_runtime.h>
#include <math.h>
#include <float.h>

// Temporal Contrast Enhancement, v7: software-pipelined dual scan.
//  - envd: y=max(x,(1-ad)x+ad*y') ; enva: y=min(x,(1-aa)x+aa*y')
//    (max/min-affine maps compose associatively -> parallel scans, exact)
//  - Direct-recurrence fixup: once a thread's resolved incoming value c is
//    known, outputs come from the plain recurrence seeded with c (no stored
//    phase-1 locals) -> fewer regs, fits 512thr @ 64 regs (32 warps/SM).
//  - Pipeline: scan3 (et_env, chunk c) and scan1 (et_d, chunk c+1) are
//    independent and share alpha_d -> ONE dual scan (shared bA/qlane/qwid,
//    one barrier, two interleaved shuffle chains for ILP). Output of chunk c
//    is fused into payload-B's fixup. 2 barriers/chunk instead of 3.
//  - 16 warps: running-squared bA ends at (q^32)^16 = exact chunk factor.

#define THREADS 512
#define RPT 8
#define CHUNK (THREADS * RPT)            // 4096
#define NWARPS (THREADS / 32)            // 16
#define T_LEN 88200
#define NCHUNK ((T_LEN + CHUNK - 1) / CHUNK)   // 22 (tail 2184, zero-padded)

template <bool MAXOP>
__device__ __forceinline__ float sel(float a, float b) {
    return MAXOP ? fmaxf(a, b) : fminf(a, b);
}

// Generic single-payload block scan: in[RPT] -> out[RPT] (may alias).
// q = alpha^RPT; qlane = q^lane; qwid = (q^32)^wid. Running bA ends at the
// chunk factor (16 warps). carry updated. One barrier.
template <bool MAXOP>
__device__ __forceinline__ void scan_single(const float* in, float* out,
                                            float alpha, float om, float q,
                                            float qlane, float qwid,
                                            float& carry, float2* sw,
                                            int lane, int wid)
{
    float v = om * in[0], yl = in[0];
    #pragma unroll
    for (int j = 1; j < RPT; j++) {
        float omm = om * in[j];
        v  = fmaf(alpha, v, omm);
        yl = sel<MAXOP>(in[j], fmaf(alpha, yl, omm));
    }
    float U = yl, V = v, bA = q;
    #pragma unroll
    for (int k = 0; k < 5; k++) {
        const int d = 1 << k;
        float uU = __shfl_up_sync(0xffffffffu, U, d);
        float uV = __shfl_up_sync(0xffffffffu, V, d);
        if (lane >= d) { U = sel<MAXOP>(U, fmaf(bA, uU, V)); V = fmaf(bA, uV, V); }
        bA *= bA;                        // ends q^32
    }
    float Ue = __shfl_up_sync(0xffffffffu, U, 1);
    float Ve = __shfl_up_sync(0xffffffffu, V, 1);

    if (lane == 31) sw[wid] = make_float2(U, V);
    __syncthreads();

    float cU = MAXOP ? -FLT_MAX : FLT_MAX, cV = 0.0f;
    if (lane < NWARPS) { float2 t = sw[lane]; cU = t.x; cV = t.y; }
    #pragma unroll
    for (int k = 0; k < 4; k++) {
        const int d = 1 << k;
        float uU = __shfl_up_sync(0xffffffffu, cU, d);
        float uV = __shfl_up_sync(0xffffffffu, cV, d);
        if (lane >= d) { cU = sel<MAXOP>(cU, fmaf(bA, uU, cV)); cV = fmaf(bA, uV, cV); }
        bA *= bA;                        // ends (q^32)^16 = chunk factor
    }
    const int src = (wid == 0) ? 0 : (wid - 1);
    float WU = __shfl_sync(0xffffffffu, cU, src);
    float WV = __shfl_sync(0xffffffffu, cV, src);
    float c_w = (wid == 0) ? carry : sel<MAXOP>(WU, fmaf(qwid, carry, WV));
    float TU = __shfl_sync(0xffffffffu, cU, NWARPS - 1);
    float TV = __shfl_sync(0xffffffffu, cV, NWARPS - 1);
    float ncar = sel<MAXOP>(TU, fmaf(bA, carry, TV));
    float y = (lane == 0) ? c_w : sel<MAXOP>(Ue, fmaf(qlane, c_w, Ve));

    // Direct-recurrence fixup seeded with resolved incoming value.
    #pragma unroll
    for (int j = 0; j < RPT; j++) {
        y = sel<MAXOP>(in[j], fmaf(alpha, y, om * in[j]));
        out[j] = y;
    }
    carry = ncar;
}

// Dual scan, both payloads alpha_d (max): shared bA/qlane/qwid, one barrier.
// Payload A (if WITH_A): PA -> QA  (et_d of next chunk, carry cA).
// Payload B: E (et of chunk at offB) -> et_env on the fly, fused final
// output  out = x * et / (et_env + regC)  (carry cB).
template <bool WITH_A>
__device__ __forceinline__ void dual_scan_ad(
    const float* PA, float* QA, const float* E,
    const float* __restrict__ xc, float* __restrict__ oc, int offB, int T,
    float ad, float omd, float q, float qlane, float qwid, float regC,
    float& cA, float& cB, float4* sw, int lane, int wid)
{
    float U1 = -FLT_MAX, V1 = 0.0f;
    if (WITH_A) {
        float v = omd * PA[0], yl = PA[0];
        #pragma unroll
        for (int j = 1; j < RPT; j++) {
            float omm = omd * PA[j];
            v  = fmaf(ad, v, omm);
            yl = fmaxf(PA[j], fmaf(ad, yl, omm));
        }
        U1 = yl; V1 = v;
    }
    float v2 = omd * E[0], yl2 = E[0];
    #pragma unroll
    for (int j = 1; j < RPT; j++) {
        float omm = omd * E[j];
        v2  = fmaf(ad, v2, omm);
        yl2 = fmaxf(E[j], fmaf(ad, yl2, omm));
    }
    float U2 = yl2, V2 = v2;

    float bA = q;
    #pragma unroll
    for (int k = 0; k < 5; k++) {
        const int d = 1 << k;
        float u2U = __shfl_up_sync(0xffffffffu, U2, d);
        float u2V = __shfl_up_sync(0xffffffffu, V2, d);
        if (WITH_A) {
            float u1U = __shfl_up_sync(0xffffffffu, U1, d);
            float u1V = __shfl_up_sync(0xffffffffu, V1, d);
            if (lane >= d) { U1 = fmaxf(U1, fmaf(bA, u1U, V1)); V1 = fmaf(bA, u1V, V1); }
        }
        if (lane >= d) { U2 = fmaxf(U2, fmaf(bA, u2U, V2)); V2 = fmaf(bA, u2V, V2); }
        bA *= bA;                        // ends q^32
    }
    float U1e = 0.f, V1e = 0.f;
    if (WITH_A) {
        U1e = __shfl_up_sync(0xffffffffu, U1, 1);
        V1e = __shfl_up_sync(0xffffffffu, V1, 1);
    }
    float U2e = __shfl_up_sync(0xffffffffu, U2, 1);
    float V2e = __shfl_up_sync(0xffffffffu, V2, 1);

    if (lane == 31) sw[wid] = make_float4(U1, V1, U2, V2);
    __syncthreads();

    float c1U = -FLT_MAX, c1V = 0.f, c2U = -FLT_MAX, c2V = 0.f;
    if (lane < NWARPS) { float4 t = sw[lane]; c1U = t.x; c1V = t.y; c2U = t.z; c2V = t.w; }
    #pragma unroll
    for (int k = 0; k < 4; k++) {
        const int d = 1 << k;
        float u2U = __shfl_up_sync(0xffffffffu, c2U, d);
        float u2V = __shfl_up_sync(0xffffffffu, c2V, d);
        if (WITH_A) {
            float u1U = __shfl_up_sync(0xffffffffu, c1U, d);
            float u1V = __shfl_up_sync(0xffffffffu, c1V, d);
            if (lane >= d) { c1U = fmaxf(c1U, fmaf(bA, u1U, c1V)); c1V = fmaf(bA, u1V, c1V); }
        }
        if (lane >= d) { c2U = fmaxf(c2U, fmaf(bA, u2U, c2V)); c2V = fmaf(bA, u2V, c2V); }
        bA *= bA;                        // ends (q^32)^16 = chunk factor
    }
    const int src = (wid == 0) ? 0 : (wid - 1);

    if (WITH_A) {
        float WU = __shfl_sync(0xffffffffu, c1U, src);
        float WV = __shfl_sync(0xffffffffu, c1V, src);
        float c_w = (wid == 0) ? cA : fmaxf(WU, fmaf(qwid, cA, WV));
        float TU = __shfl_sync(0xffffffffu, c1U, NWARPS - 1);
        float TV = __shfl_sync(0xffffffffu, c1V, NWARPS - 1);
        float ncar = fmaxf(TU, fmaf(bA, cA, TV));
        float y = (lane == 0) ? c_w : fmaxf(U1e, fmaf(qlane, c_w, V1e));
        #pragma unroll
        for (int j = 0; j < RPT; j++) {
            y = fmaxf(PA[j], fmaf(ad, y, omd * PA[j]));
            QA[j] = y;
        }
        cA = ncar;
    }
    {
        float WU = __shfl_sync(0xffffffffu, c2U, src);
        float WV = __shfl_sync(0xffffffffu, c2V, src);
        float c_w = (wid == 0) ? cB : fmaxf(WU, fmaf(qwid, cB, WV));
        float TU = __shfl_sync(0xffffffffu, c2U, NWARPS - 1);
        float TV = __shfl_sync(0xffffffffu, c2V, NWARPS - 1);
        float ncar = fmaxf(TU, fmaf(bA, cB, TV));
        float z = (lane == 0) ? c_w : fmaxf(U2e, fmaf(qlane, c_w, V2e));
        // Fixup + fused output, one float4 group at a time (low reg pressure)
        if (offB + RPT <= T) {
            #pragma unroll
            for (int g = 0; g < RPT / 4; g++) {
                float4 xv = *reinterpret_cast<const float4*>(xc + offB + 4 * g);
                float4 r;
                float et;
                et = E[4*g+0]; z = fmaxf(et, fmaf(ad, z, omd * et));
                r.x = xv.x * __fdividef(et, z + regC);
                et = E[4*g+1]; z = fmaxf(et, fmaf(ad, z, omd * et));
                r.y = xv.y * __fdividef(et, z + regC);
                et = E[4*g+2]; z = fmaxf(et, fmaf(ad, z, omd * et));
                r.z = xv.z * __fdividef(et, z + regC);
                et = E[4*g+3]; z = fmaxf(et, fmaf(ad, z, omd * et));
                r.w = xv.w * __fdividef(et, z + regC);
                *reinterpret_cast<float4*>(oc + offB + 4 * g) = r;
            }
        } else {
            #pragma unroll
            for (int j = 0; j < RPT; j++) {
                float et = E[j];
                z = fmaxf(et, fmaf(ad, z, omd * et));
                if (offB + j < T)
                    oc[offB + j] = xc[offB + j] * __fdividef(et, z + regC);
            }
        }
        cB = ncar;
    }
}

__device__ __forceinline__ void load_abs_chunk(const float* __restrict__ xc,
                                               int off, int T, float* P)
{
    #pragma unroll
    for (int g = 0; g < RPT / 4; g++) {
        const int o = off + g * 4;
        float4 v = make_float4(0.f, 0.f, 0.f, 0.f);
        if (o + 4 <= T) {
            v = *reinterpret_cast<const float4*>(xc + o);
        } else if (o < T) {
            v.x = xc[o];
            if (o + 1 < T) v.y = xc[o + 1];
            if (o + 2 < T) v.z = xc[o + 2];
        }
        P[4*g+0] = fabsf(v.x); P[4*g+1] = fabsf(v.y);
        P[4*g+2] = fabsf(v.z); P[4*g+3] = fabsf(v.w);
    }
}

__global__ void __launch_bounds__(THREADS, 2)
tce_kernel(const float* __restrict__ x,
           const float* __restrict__ p_tauA,
           const float* __restrict__ p_tauD,
           const float* __restrict__ p_nu,
           const float* __restrict__ p_dbr,
           float* __restrict__ out, int T)
{
    __shared__ float4 sw4[NWARPS];       // dual-scan aggregates
    __shared__ float2 sw1[NWARPS];       // prologue scan1
    __shared__ float2 sw2[NWARPS];       // scan2 (all uses)

    const int lane = threadIdx.x & 31;
    const int wid  = threadIdx.x >> 5;
    const long long ch = blockIdx.x;
    const float* xc = x + ch * (long long)T;
    float* oc = out + ch * (long long)T;

    // Scalar params (replicate reference clip chain)
    float tauA = fminf(fmaxf(p_tauA[0], 1.0f), 100.0f);
    tauA = fminf(fmaxf(tauA, 0.1f), 1000.0f) * 0.001f;
    const float aa = expf(-1.0f / (tauA * 44100.0f));
    float tauD = fminf(fmaxf(p_tauD[0], 1.0f), 100.0f);
    tauD = fminf(fmaxf(tauD, 0.1f), 1000.0f) * 0.001f;
    const float ad = expf(-1.0f / (tauD * 44100.0f));
    const float nuAmp = exp10f(fminf(fmaxf(p_nu[0], -60.0f), 0.0f) * 0.05f);
    const float regC  = exp10f(fminf(fmaxf(p_dbr[0], -120.0f), -60.0f) * 0.05f);
    const float omd = 1.0f - ad;
    const float oma = 1.0f - aa;

    // q = alpha^8 (3 squarings); per-lane q^lane; per-warp (q^32)^wid.
    float qd = ad * ad; qd *= qd; qd *= qd;              // ad^8
    float qa = aa * aa; qa *= qa; qa *= qa;              // aa^8
    float qdlane = 1.0f, qalane = 1.0f;
    for (int i = 0; i < lane; i++) { qdlane *= qd; qalane *= qa; }
    float qwd = qd * qd; qwd *= qwd; qwd *= qwd; qwd *= qwd; qwd *= qwd; // qd^32
    float qwa = qa * qa; qwa *= qwa; qwa *= qwa; qwa *= qwa; qwa *= qwa; // qa^32
    float qwidd = 1.0f, qwida = 1.0f;
    for (int i = 0; i < wid; i++) { qwidd *= qwd; qwida *= qwa; }

    float cd = 0.0f, ca = 0.0f, ce = 0.0f;

    float P[RPT], Q[RPT], E[RPT];
    const int tb = (int)threadIdx.x * RPT;

    // ── Prologue: chunk 0 through scan1/scan2/et ──
    load_abs_chunk(xc, tb, T, P);
    scan_single<true >(P, Q, ad, omd, qd, qdlane, qwidd, cd, sw1, lane, wid);
    scan_single<false>(Q, P, aa, oma, qa, qalane, qwida, ca, sw2, lane, wid);
    #pragma unroll
    for (int j = 0; j < RPT; j++) E[j] = fmaxf(Q[j] - P[j] - nuAmp, 0.0f);

    // ── Main loop: dual scan [scan3(c) + output(c)] + [scan1(c+1)] ──
    for (int c = 0; c < NCHUNK - 1; c++) {
        const int offNext = (c + 1) * CHUNK + tb;
        load_abs_chunk(xc, offNext, T, P);
        dual_scan_ad<true>(P, Q, E, xc, oc, c * CHUNK + tb, T,
                           ad, omd, qd, qdlane, qwidd, regC,
                           cd, ce, sw4, lane, wid);
        scan_single<false>(Q, P, aa, oma, qa, qalane, qwida, ca, sw2, lane, wid);
        #pragma unroll
        for (int j = 0; j < RPT; j++) E[j] = fmaxf(Q[j] - P[j] - nuAmp, 0.0f);
    }

    // ── Epilogue: scan3 + output for the last chunk ──
    dual_scan_ad<false>(P, Q, E, xc, oc, (NCHUNK - 1) * CHUNK + tb, T,
                        ad, omd, qd, qdlane, qwidd, regC,
                        cd, ce, sw4, lane, wid);
}

extern "C" void kernel_launch(void* const* d_in, const int* in_sizes, int n_in,
                              void* d_out, int out_size)
{
    const float* x      = (const float*)d_in[0];
    const float* tauAtc = (const float*)d_in[1];
    const float* tauDtc = (const float*)d_in[2];
    const float* nu     = (const float*)d_in[3];
    const float* dbr    = (const float*)d_in[4];
    float* out = (float*)d_out;

    const int T = T_LEN;
    const int channels = in_sizes[0] / T;   // 256

    tce_kernel<<<channels, THREADS>>>(x, tauAtc, tauDtc, nu, dbr, out, T);
}